// round 6
// baseline (speedup 1.0000x reference)
#include <cuda_runtime.h>
#include <cuda_fp16.h>
#include <cstdint>

#define NMAX 100000
#define EMAX 2000000

// ---- scratch (__device__ globals; no allocations allowed) ----
__device__ int    g_deg[NMAX];
__device__ float  g_dinv[NMAX];
__device__ int    g_ptr[NMAX + 1];
__device__ int    g_cursor[NMAX];
__device__ unsigned long long g_state[128];   // lookback scan state
__device__ int    g_csr[EMAX];
__device__ uint4  g_g1h[NMAX * 8];    // x@W1 raw (no dinv), fp16 [N,64] = 8 uint4/row
__device__ float  g_h1[NMAX * 64];    // relu(dinv*agg1 + b1), fp32
__device__ float4 g_g2[NMAX * 8];     // h1@W2 raw fp32 [N,32]
__device__ int    g_idx64;

// ---------- K1: detect dtype + deg init + scan-state reset ----------
__global__ void k_init(const unsigned int* __restrict__ w, int n) {
    int i = blockIdx.x * blockDim.x + threadIdx.x;
    if (i == 0) {
        int all0 = 1;
        for (int k = 1; k < 129; k += 2) all0 &= (w[k] == 0u);
        g_idx64 = all0;
    }
    if (i < 128) g_state[i] = 0ULL;
    if (i < n) g_deg[i] = 1;   // self-loop
}

// ---------- gemm1 tile: 256 nodes x 64 feats, 256 thr, thread 8x8 ----------
__device__ __forceinline__ void gemm1_tile(const float* __restrict__ x,
                                           const float* __restrict__ W1,
                                           int n, int tile) {
    __shared__ __align__(16) float xs[32 * 260];   // [k][node], padded
    __shared__ __align__(16) float ws[32 * 64];    // [k][feat]
    int tid = threadIdx.x;
    int fx = tid & 7, ty = tid >> 3;
    int nbase = tile * 256;
    float acc[8][8];
#pragma unroll
    for (int i = 0; i < 8; i++)
#pragma unroll
        for (int j = 0; j < 8; j++) acc[i][j] = 0.f;
    const float4* x4 = (const float4*)x;
    for (int k0 = 0; k0 < 128; k0 += 32) {
        __syncthreads();
        int node = nbase + tid;
        int nodec = node < n ? node : n - 1;
        const float4* row = x4 + (size_t)nodec * 32 + (k0 >> 2);
#pragma unroll
        for (int q = 0; q < 8; q++) {
            float4 v = row[q];
            int kk = q * 4;
            xs[(kk + 0) * 260 + tid] = v.x;
            xs[(kk + 1) * 260 + tid] = v.y;
            xs[(kk + 2) * 260 + tid] = v.z;
            xs[(kk + 3) * 260 + tid] = v.w;
        }
        const float4* wsrc = (const float4*)W1 + k0 * 16;
        float4* wd = (float4*)ws;
        wd[tid] = wsrc[tid];
        wd[256 + tid] = wsrc[256 + tid];
        __syncthreads();
#pragma unroll 4
        for (int kk = 0; kk < 32; kk++) {
            float4 xa = *(const float4*)&xs[kk * 260 + ty * 8];
            float4 xb = *(const float4*)&xs[kk * 260 + ty * 8 + 4];
            float4 wa = *(const float4*)&ws[kk * 64 + fx * 8];
            float4 wb = *(const float4*)&ws[kk * 64 + fx * 8 + 4];
            float xv[8] = {xa.x, xa.y, xa.z, xa.w, xb.x, xb.y, xb.z, xb.w};
            float wv[8] = {wa.x, wa.y, wa.z, wa.w, wb.x, wb.y, wb.z, wb.w};
#pragma unroll
            for (int i = 0; i < 8; i++)
#pragma unroll
                for (int j = 0; j < 8; j++) acc[i][j] += xv[i] * wv[j];
        }
    }
#pragma unroll
    for (int i = 0; i < 8; i++) {
        int node = nbase + ty * 8 + i;
        if (node < n) {
            union { __half2 h[4]; uint4 u; } uu;
            uu.h[0] = __floats2half2_rn(acc[i][0], acc[i][1]);
            uu.h[1] = __floats2half2_rn(acc[i][2], acc[i][3]);
            uu.h[2] = __floats2half2_rn(acc[i][4], acc[i][5]);
            uu.h[3] = __floats2half2_rn(acc[i][6], acc[i][7]);
            g_g1h[(size_t)node * 8 + fx] = uu.u;
        }
    }
}

// ---------- K2: gemm1 part A (blocks [0,ga)) || deg_count ----------
__global__ __launch_bounds__(256) void k_gemm1_deg(
        const float* __restrict__ x, const float* __restrict__ W1,
        const void* __restrict__ ei, int e, int n, int ga) {
    if ((int)blockIdx.x < ga) { gemm1_tile(x, W1, n, blockIdx.x); return; }
    int i = ((int)blockIdx.x - ga) * 256 + threadIdx.x;
    if (i >= e) return;
    int d;
    if (g_idx64) d = (int)((const long long*)ei)[(size_t)e + i];
    else         d = ((const int*)ei)[(size_t)e + i];
    atomicAdd(&g_deg[d], 1);
}

// ---------- K3: single-pass decoupled-lookback scan + dinv + cursor ----------
__global__ __launch_bounds__(256) void k_scan(int n) {
    __shared__ int tsum[256];
    __shared__ int sh_excl;
    int t = threadIdx.x;
    int tile = blockIdx.x;
    int base = tile * 1024 + t * 4;
    int v[4], s = 0;
#pragma unroll
    for (int q = 0; q < 4; q++) {
        int idx = base + q;
        v[q] = (idx < n) ? g_deg[idx] : 0;
        s += v[q];
    }
    tsum[t] = s;
    __syncthreads();
    for (int off = 1; off < 256; off <<= 1) {
        int xx = (t >= off) ? tsum[t - off] : 0;
        __syncthreads();
        tsum[t] += xx;
        __syncthreads();
    }
    int incl = tsum[t];
    int agg = tsum[255];
    if (t == 0) {
        long long excl = 0;
        if (tile > 0) {
            atomicExch(&g_state[tile], (1ULL << 32) | (unsigned long long)(unsigned)agg);
            int i = tile - 1;
            while (1) {
                unsigned long long p = atomicAdd(&g_state[i], 0ULL);
                unsigned f = (unsigned)(p >> 32);
                if (f == 0) continue;
                excl += (long long)(unsigned)(p & 0xffffffffu);
                if (f == 2) break;
                i--;
            }
        }
        atomicExch(&g_state[tile], (2ULL << 32) | (unsigned long long)(unsigned)(excl + agg));
        sh_excl = (int)excl;
    }
    __syncthreads();
    int run = sh_excl + incl - s;
#pragma unroll
    for (int q = 0; q < 4; q++) {
        int idx = base + q;
        if (idx < n) {
            g_ptr[idx] = run;
            g_cursor[idx] = run;
            g_dinv[idx] = rsqrtf((float)v[q]);
            run += v[q];
            if (idx == n - 1) g_ptr[n] = run;
        }
    }
}

// ---------- K4: gemm1 part B (blocks [0,gb-ga)) || CSR fill ----------
__global__ __launch_bounds__(256) void k_gemm1_fill(
        const float* __restrict__ x, const float* __restrict__ W1,
        const void* __restrict__ ei, int e, int n, int ga, int gb) {
    int nb = gb - ga;
    if ((int)blockIdx.x < nb) { gemm1_tile(x, W1, n, ga + blockIdx.x); return; }
    int i = ((int)blockIdx.x - nb) * 256 + threadIdx.x;
    if (i >= e) return;
    int s, d;
    if (g_idx64) {
        const long long* p = (const long long*)ei;
        s = (int)p[i]; d = (int)p[(size_t)e + i];
    } else {
        const int* p = (const int*)ei;
        s = p[i]; d = p[(size_t)e + i];
    }
    int pos = atomicAdd(&g_cursor[d], 1);
    g_csr[pos] = s;
}

// ---------- K5: pull1, warp-per-node (8 feat-lanes x 4 edge-slots) ----------
__global__ __launch_bounds__(256) void k_pull1(const float* __restrict__ b1, int n) {
    int node = (blockIdx.x * blockDim.x + threadIdx.x) >> 5;
    if (node >= n) return;
    int lane = threadIdx.x & 31;
    int c = lane & 7, eslot = lane >> 3;
    float dvd = g_dinv[node];
    float a[8];
    if (eslot == 0) {   // self-loop seed: dinv[d]*g1[d]
        uint4 sv = g_g1h[(size_t)node * 8 + c];
        const __half2* h = (const __half2*)&sv;
#pragma unroll
        for (int q = 0; q < 4; q++) {
            float2 f = __half22float2(h[q]);
            a[q * 2] = dvd * f.x; a[q * 2 + 1] = dvd * f.y;
        }
    } else {
#pragma unroll
        for (int q = 0; q < 8; q++) a[q] = 0.f;
    }
    int beg = g_ptr[node], end = g_ptr[node + 1] - 1;  // exclude self slot budget
    for (int i = beg + eslot; i < end; i += 4) {
        int s = g_csr[i];
        float dv = g_dinv[s];
        uint4 wv = g_g1h[(size_t)s * 8 + c];
        const __half2* h = (const __half2*)&wv;
#pragma unroll
        for (int q = 0; q < 4; q++) {
            float2 f = __half22float2(h[q]);
            a[q * 2]     = fmaf(dv, f.x, a[q * 2]);
            a[q * 2 + 1] = fmaf(dv, f.y, a[q * 2 + 1]);
        }
    }
#pragma unroll
    for (int q = 0; q < 8; q++) {
        a[q] += __shfl_xor_sync(0xffffffffu, a[q], 8);
        a[q] += __shfl_xor_sync(0xffffffffu, a[q], 16);
    }
    if (eslot == 0) {
        float4 blo = ((const float4*)b1)[c * 2];
        float4 bhi = ((const float4*)b1)[c * 2 + 1];
        float4 lo, hi;
        lo.x = fmaxf(fmaf(dvd, a[0], blo.x), 0.f);
        lo.y = fmaxf(fmaf(dvd, a[1], blo.y), 0.f);
        lo.z = fmaxf(fmaf(dvd, a[2], blo.z), 0.f);
        lo.w = fmaxf(fmaf(dvd, a[3], blo.w), 0.f);
        hi.x = fmaxf(fmaf(dvd, a[4], bhi.x), 0.f);
        hi.y = fmaxf(fmaf(dvd, a[5], bhi.y), 0.f);
        hi.z = fmaxf(fmaf(dvd, a[6], bhi.z), 0.f);
        hi.w = fmaxf(fmaf(dvd, a[7], bhi.w), 0.f);
        *(float4*)&g_h1[(size_t)node * 64 + c * 8]     = lo;
        *(float4*)&g_h1[(size_t)node * 64 + c * 8 + 4] = hi;
    }
}

// ---------- K6: GEMM2: g2 = h1 @ W2 (raw, no dinv), tile 128x32 ----------
__global__ __launch_bounds__(128) void k_gemm2(const float* __restrict__ W2, int n) {
    __shared__ __align__(16) float hs[64 * 136];
    __shared__ __align__(16) float ws[64 * 32];
    int fx = threadIdx.x, ty = threadIdx.y;
    int tid = ty * 8 + fx;
    int nbase = blockIdx.x * 128;
    float acc[8][4];
#pragma unroll
    for (int i = 0; i < 8; i++)
#pragma unroll
        for (int j = 0; j < 4; j++) acc[i][j] = 0.f;
    {
        int node = nbase + tid;
        int nodec = node < n ? node : (n - 1);
        const float4* row = (const float4*)&g_h1[(size_t)nodec * 64];
#pragma unroll
        for (int q = 0; q < 16; q++) {
            float4 v = row[q];
            int kk = q * 4;
            hs[(kk + 0) * 136 + tid] = v.x;
            hs[(kk + 1) * 136 + tid] = v.y;
            hs[(kk + 2) * 136 + tid] = v.z;
            hs[(kk + 3) * 136 + tid] = v.w;
        }
        const float4* wsrc = (const float4*)W2;
        float4* wd = (float4*)ws;
#pragma unroll
        for (int q = 0; q < 4; q++) wd[q * 128 + tid] = wsrc[q * 128 + tid];
    }
    __syncthreads();
#pragma unroll 4
    for (int kk = 0; kk < 64; kk++) {
        float4 xa = *(const float4*)&hs[kk * 136 + ty * 8];
        float4 xb = *(const float4*)&hs[kk * 136 + ty * 8 + 4];
        float4 w  = *(const float4*)&ws[kk * 32 + fx * 4];
        float xv[8] = {xa.x, xa.y, xa.z, xa.w, xb.x, xb.y, xb.z, xb.w};
        float wv[4] = {w.x, w.y, w.z, w.w};
#pragma unroll
        for (int i = 0; i < 8; i++)
#pragma unroll
            for (int j = 0; j < 4; j++) acc[i][j] += xv[i] * wv[j];
    }
#pragma unroll
    for (int i = 0; i < 8; i++) {
        int node = nbase + ty * 8 + i;
        if (node < n)
            g_g2[(size_t)node * 8 + fx] =
                make_float4(acc[i][0], acc[i][1], acc[i][2], acc[i][3]);
    }
}

// ---------- K7: pull2 (warp-per-node) + mu/logvar heads fused ----------
__global__ __launch_bounds__(256) void k_pull2(const float* __restrict__ b2,
        const float* __restrict__ Wmu, const float* __restrict__ bmu,
        const float* __restrict__ Wlv, const float* __restrict__ blv,
        float* __restrict__ out, int n) {
    __shared__ float hsm[8 * 33];
    __shared__ float wm[32 * 32];
    __shared__ float wl[32 * 32];
    int tid = threadIdx.x;
#pragma unroll
    for (int q = 0; q < 4; q++) {
        wm[q * 256 + tid] = Wmu[q * 256 + tid];
        wl[q * 256 + tid] = Wlv[q * 256 + tid];
    }
    int j = tid >> 5, lane = tid & 31;
    int c = lane & 7, eslot = lane >> 3;
    int node = blockIdx.x * 8 + j;
    int nodec = node < n ? node : (n - 1);
    float dvd = g_dinv[nodec];
    float4 acc;
    if (eslot == 0) {
        float4 sv = g_g2[(size_t)nodec * 8 + c];
        acc = make_float4(dvd * sv.x, dvd * sv.y, dvd * sv.z, dvd * sv.w);
    } else {
        acc = make_float4(0.f, 0.f, 0.f, 0.f);
    }
    int beg = g_ptr[nodec], end = g_ptr[nodec + 1] - 1;
    for (int i = beg + eslot; i < end; i += 4) {
        int s = g_csr[i];
        float dv = g_dinv[s];
        float4 v = g_g2[(size_t)s * 8 + c];
        acc.x = fmaf(dv, v.x, acc.x);
        acc.y = fmaf(dv, v.y, acc.y);
        acc.z = fmaf(dv, v.z, acc.z);
        acc.w = fmaf(dv, v.w, acc.w);
    }
    acc.x += __shfl_xor_sync(0xffffffffu, acc.x, 8);
    acc.y += __shfl_xor_sync(0xffffffffu, acc.y, 8);
    acc.z += __shfl_xor_sync(0xffffffffu, acc.z, 8);
    acc.w += __shfl_xor_sync(0xffffffffu, acc.w, 8);
    acc.x += __shfl_xor_sync(0xffffffffu, acc.x, 16);
    acc.y += __shfl_xor_sync(0xffffffffu, acc.y, 16);
    acc.z += __shfl_xor_sync(0xffffffffu, acc.z, 16);
    acc.w += __shfl_xor_sync(0xffffffffu, acc.w, 16);
    if (eslot == 0) {
        float4 bb = ((const float4*)b2)[c];
        hsm[j * 33 + c * 4 + 0] = fmaf(dvd, acc.x, bb.x);
        hsm[j * 33 + c * 4 + 1] = fmaf(dvd, acc.y, bb.y);
        hsm[j * 33 + c * 4 + 2] = fmaf(dvd, acc.z, bb.z);
        hsm[j * 33 + c * 4 + 3] = fmaf(dvd, acc.w, bb.w);
    }
    __syncthreads();
    // heads: thread (j, lane) -> mu[node][lane], logvar[node][lane]
    float mu = bmu[lane], lv = blv[lane];
    const float* hr = &hsm[j * 33];
#pragma unroll
    for (int k = 0; k < 32; k++) {
        float hv = hr[k];
        mu = fmaf(hv, wm[k * 32 + lane], mu);
        lv = fmaf(hv, wl[k * 32 + lane], lv);
    }
    if (node < n) {
        out[(size_t)node * 32 + lane] = mu;
        out[(size_t)n * 32 + (size_t)node * 32 + lane] = lv;
    }
}

extern "C" void kernel_launch(void* const* d_in, const int* in_sizes, int n_in,
                              void* d_out, int out_size) {
    const float* x   = (const float*)d_in[0];
    const void*  ei  = d_in[1];
    const float* W1  = (const float*)d_in[2];
    const float* b1  = (const float*)d_in[3];
    const float* W2  = (const float*)d_in[4];
    const float* b2  = (const float*)d_in[5];
    const float* Wmu = (const float*)d_in[6];
    const float* bmu = (const float*)d_in[7];
    const float* Wlv = (const float*)d_in[8];
    const float* blv = (const float*)d_in[9];
    float* out = (float*)d_out;

    int n = in_sizes[0] / 128;   // 100000
    int e = in_sizes[1] / 2;     // 1600000

    int DB = (e + 255) / 256;          // deg / fill blocks
    int GB = (n + 255) / 256;          // gemm1 tiles (256 nodes each)
    int GA = (GB * 2) / 5;             // gemm1 tiles co-launched with deg_count
    if (GA < 1) GA = 1;
    if (GA > GB) GA = GB;
    int ntiles = (n + 1023) / 1024;    // <= 128

    k_init<<<(n + 255) / 256, 256>>>((const unsigned int*)ei, n);
    k_gemm1_deg<<<GA + DB, 256>>>(x, W1, ei, e, n, GA);
    k_scan<<<ntiles, 256>>>(n);
    k_gemm1_fill<<<(GB - GA) + DB, 256>>>(x, W1, ei, e, n, GA, GB);
    k_pull1<<<(n + 7) / 8, 256>>>(b1, n);
    dim3 gth(8, 16);
    k_gemm2<<<(n + 127) / 128, gth>>>(W2, n);
    k_pull2<<<(n + 7) / 8, 256>>>(b2, Wmu, bmu, Wlv, blv, out, n);
}